// round 7
// baseline (speedup 1.0000x reference)
#include <cuda_runtime.h>
#include <cuda_fp16.h>
#include <math.h>
#include <stdint.h>

// ---------------- problem constants ----------------
#define NB      8
#define HH      56
#define WW      56
#define LSEQ    3136
#define BLTOT   25088
#define CDIM    384
#define DINNER  768
#define DSTATE  64
#define NHM     12
#define DINPROJ 1676
#define CONVDIM 896
#define NHA     12
#define NWIN    512
#define MTILES  196   // BLTOT/128

// ---------------- fp32 scratch ----------------
__device__ float g_zx   [(size_t)BLTOT * DINPROJ];
__device__ float g_xs   [(size_t)BLTOT * DINNER];
__device__ float g_Bm   [(size_t)BLTOT * DSTATE];
__device__ float g_Cm   [(size_t)BLTOT * DSTATE];
__device__ float g_dt   [(size_t)BLTOT * NHM];
__device__ float g_dA   [(size_t)BLTOT * NHM];
__device__ float g_y    [(size_t)BLTOT * DINNER];
__device__ float g_gate [(size_t)BLTOT * NHA];
__device__ float g_x2   [(size_t)BLTOT * CDIM];

// ---------------- fp16 activation scratch ----------------
__device__ __half b_xn  [(size_t)BLTOT * CDIM];
__device__ __half b_g   [(size_t)BLTOT * DINNER];
__device__ __half b_ag  [(size_t)BLTOT * CDIM];
__device__ __half b_cat [(size_t)BLTOT * DINNER];   // [mamba | attn]
__device__ __half b_h1  [(size_t)BLTOT * 1536];
__device__ __half b_xn2 [(size_t)BLTOT * CDIM];
__device__ __half b_qkv [(size_t)BLTOT * 1152];

// ---------------- fp16 transposed weights [N][K] ----------------
__device__ __half w_in  [(size_t)DINPROJ * CDIM];
__device__ __half w_qkv [(size_t)1152 * CDIM];
__device__ __half w_out [(size_t)CDIM * DINNER];
__device__ __half w_prj [(size_t)CDIM * CDIM];
__device__ __half w_fus [(size_t)CDIM * DINNER];
__device__ __half w_fc1 [(size_t)1536 * CDIM];
__device__ __half w_fc2 [(size_t)CDIM * 1536];

__device__ __forceinline__ uint32_t smem_u32(const void* p) {
    uint32_t a;
    asm("{ .reg .u64 t; cvta.to.shared.u64 t, %1; cvt.u32.u64 %0, t; }" : "=r"(a) : "l"(p));
    return a;
}

// ================= mma.sync fp16 GEMM (round-6 winner, unchanged) =================
#define BKG   64
#define ASTR  72            // BK + 8 pad (fp16); 144B row stride
#define MATSZ (128 * ASTR)  // 9216 elems
#define STAGESZ (2 * MATSZ) // A, B
#define GEMM_SMEM (2 * STAGESZ * 2)  // 73728 bytes

__device__ __forceinline__ void ldsm4(uint32_t& r0, uint32_t& r1, uint32_t& r2, uint32_t& r3, uint32_t a) {
    asm volatile("ldmatrix.sync.aligned.m8n8.x4.shared.b16 {%0,%1,%2,%3}, [%4];"
                 : "=r"(r0), "=r"(r1), "=r"(r2), "=r"(r3) : "r"(a));
}
__device__ __forceinline__ void mma16816(float* c, const uint32_t* a, const uint32_t* b) {
    asm volatile("mma.sync.aligned.m16n8k16.row.col.f32.f16.f16.f32 "
                 "{%0,%1,%2,%3}, {%4,%5,%6,%7}, {%8,%9}, {%0,%1,%2,%3};"
                 : "+f"(c[0]), "+f"(c[1]), "+f"(c[2]), "+f"(c[3])
                 : "r"(a[0]), "r"(a[1]), "r"(a[2]), "r"(a[3]), "r"(b[0]), "r"(b[1]));
}
__device__ __forceinline__ void cpasync16(uint32_t dst, const void* src, uint32_t sz) {
    asm volatile("cp.async.cg.shared.global [%0], [%1], 16, %2;"
                 :: "r"(dst), "l"(src), "r"(sz) : "memory");
}

__global__ void __launch_bounds__(256, 2)
mma_gemm(const __half* __restrict__ Aw, const __half* __restrict__ Bw,
         const float* __restrict__ bias, const float* __restrict__ res,
         float* __restrict__ Cf, __half* __restrict__ Chalf,
         int ldh, int M, int N, int K, int act)
{
    extern __shared__ __align__(16) __half smem[];
    const int tid = threadIdx.x;
    const int wid = tid >> 5, lane = tid & 31;
    const int warp_m = wid & 1, warp_n = wid >> 1;
    const int m0 = blockIdx.y * 128, n0 = blockIdx.x * 128;

    const int lrow = tid >> 1, lseg = tid & 1;
    const bool bvalid = (n0 + lrow) < N;
    const uint32_t sbase = smem_u32(smem);

    float acc[4][4][4];
#pragma unroll
    for (int i = 0; i < 4; i++)
#pragma unroll
        for (int j = 0; j < 4; j++)
#pragma unroll
            for (int e = 0; e < 4; e++) acc[i][j][e] = 0.f;

    const int nch = K / BKG;

    auto load_stage = [&](int ch, int st) {
        const int k0 = ch * BKG;
        uint32_t so = (uint32_t)(st * STAGESZ + lrow * ASTR + lseg * 32) * 2;
        const __half* ga = Aw + (size_t)(m0 + lrow) * K + k0 + lseg * 32;
        const __half* gb = Bw + (size_t)(n0 + lrow) * K + k0 + lseg * 32;
        uint32_t bs = bvalid ? 16u : 0u;
#pragma unroll
        for (int u = 0; u < 4; u++) {
            cpasync16(sbase + so + u * 16,             ga + u * 8, 16u);
            cpasync16(sbase + so + MATSZ * 2 + u * 16, gb + u * 8, bs);
        }
    };

    load_stage(0, 0);
    asm volatile("cp.async.commit_group;" ::: "memory");

    for (int ch = 0; ch < nch; ch++) {
        const int st = ch & 1;
        if (ch + 1 < nch) load_stage(ch + 1, st ^ 1);
        asm volatile("cp.async.commit_group;" ::: "memory");
        asm volatile("cp.async.wait_group 1;" ::: "memory");
        __syncthreads();

        const uint32_t sA = sbase + (uint32_t)(st * STAGESZ) * 2;
        const uint32_t sB = sA + MATSZ * 2;
        const int lr = lane & 15;
        const int lk = (lane >> 4) << 3;

#pragma unroll
        for (int ks = 0; ks < BKG; ks += 16) {
            uint32_t bh[4][2];
#pragma unroll
            for (int np = 0; np < 2; np++) {
                uint32_t off = (uint32_t)((warp_n * 32 + np * 16 + lr) * ASTR + ks + lk) * 2;
                uint32_t r0, r1, r2, r3;
                ldsm4(r0, r1, r2, r3, sB + off);
                bh[np*2+0][0] = r0; bh[np*2+0][1] = r2;
                bh[np*2+1][0] = r1; bh[np*2+1][1] = r3;
            }
#pragma unroll
            for (int mt = 0; mt < 4; mt++) {
                uint32_t off = (uint32_t)((warp_m * 64 + mt * 16 + lr) * ASTR + ks + lk) * 2;
                uint32_t a[4];
                ldsm4(a[0], a[1], a[2], a[3], sA + off);
#pragma unroll
                for (int nt = 0; nt < 4; nt++) mma16816(acc[mt][nt], a, bh[nt]);
            }
        }
        __syncthreads();
    }

    // epilogue
    const int mrow = m0 + warp_m * 64 + (lane >> 2);
    const int ncol = n0 + warp_n * 32 + (lane & 3) * 2;
#pragma unroll
    for (int mt = 0; mt < 4; mt++) {
#pragma unroll
        for (int nt = 0; nt < 4; nt++) {
#pragma unroll
            for (int e = 0; e < 4; e++) {
                int r = mrow + mt * 16 + ((e >> 1) ? 8 : 0);
                int c = ncol + nt * 8 + (e & 1);
                if (c < N) {
                    float v = acc[mt][nt][e];
                    if (bias) v += bias[c];
                    if (act)  v = 0.5f * v * (1.f + erff(v * 0.70710678118654752f));
                    if (res)  v += res[(size_t)r * N + c];
                    if (Cf)    Cf[(size_t)r * N + c] = v;
                    if (Chalf) Chalf[(size_t)r * ldh + c] = __float2half_rn(v);
                }
            }
        }
    }
}

// ---------------- weight transpose + fp16: W[K][N] -> out[N][K] ----------------
__global__ void wconv_kernel(const float* __restrict__ W, __half* __restrict__ o, int K, int N)
{
    long idx = (long)blockIdx.x * blockDim.x + threadIdx.x;
    if (idx >= (long)K * N) return;
    int k = (int)(idx % K);
    long n = idx / K;
    o[idx] = __float2half_rn(W[(size_t)k * N + n]);
}

// ---------------- LayerNorm (384) -> fp16, warp per row ----------------
__global__ void ln_kernel(const float* __restrict__ x, const float* __restrict__ w,
                          const float* __restrict__ b, __half* __restrict__ oh)
{
    int row  = blockIdx.x * 8 + (threadIdx.x >> 5);
    int lane = threadIdx.x & 31;
    if (row >= BLTOT) return;
    const float* xr = x + (size_t)row * CDIM;
    float v[12];
    float s = 0.f;
#pragma unroll
    for (int i = 0; i < 3; i++) {
        float4 t = *(const float4*)(xr + i * 128 + lane * 4);
        v[i*4+0]=t.x; v[i*4+1]=t.y; v[i*4+2]=t.z; v[i*4+3]=t.w;
        s += t.x + t.y + t.z + t.w;
    }
#pragma unroll
    for (int o = 16; o; o >>= 1) s += __shfl_xor_sync(0xffffffffu, s, o);
    float mu = s * (1.f / CDIM);
    float ss = 0.f;
#pragma unroll
    for (int i = 0; i < 12; i++) { float d = v[i] - mu; ss += d * d; }
#pragma unroll
    for (int o = 16; o; o >>= 1) ss += __shfl_xor_sync(0xffffffffu, ss, o);
    float rstd = rsqrtf(ss * (1.f / CDIM) + 1e-5f);
#pragma unroll
    for (int i = 0; i < 3; i++) {
        int c = i * 128 + lane * 4;
        float4 wv = *(const float4*)(w + c);
        float4 bv = *(const float4*)(b + c);
        size_t o0 = (size_t)row * CDIM + c;
        oh[o0+0] = __float2half_rn((v[i*4+0]-mu)*rstd*wv.x + bv.x);
        oh[o0+1] = __float2half_rn((v[i*4+1]-mu)*rstd*wv.y + bv.y);
        oh[o0+2] = __float2half_rn((v[i*4+2]-mu)*rstd*wv.z + bv.z);
        oh[o0+3] = __float2half_rn((v[i*4+3]-mu)*rstd*wv.w + bv.w);
    }
}

// ---------------- fused depthwise conv(k=4)+SiLU+split  AND  dt/dA ----------------
// covers 908 "columns" per (b,l) row: [0,896) conv outputs, [896,908) dt heads
#define FCOLS (CONVDIM + NHM)   // 908
__global__ void convdt_kernel(const float* __restrict__ zx, const float* __restrict__ cw,
                              const float* __restrict__ cb,
                              const float* __restrict__ dtb, const float* __restrict__ Alog,
                              float* __restrict__ xs, float* __restrict__ Bout,
                              float* __restrict__ Cout,
                              float* __restrict__ dt, float* __restrict__ dA)
{
    long idx = (long)blockIdx.x * blockDim.x + threadIdx.x;
    if (idx >= (long)BLTOT * FCOLS) return;
    int c  = (int)(idx % FCOLS);
    long bl = idx / FCOLS;
    if (c < CONVDIM) {
        int l  = (int)(bl % LSEQ);
        float acc = cb[c];
        const float w0 = cw[c*4+0], w1 = cw[c*4+1], w2 = cw[c*4+2], w3 = cw[c*4+3];
        const float* base = zx + (size_t)bl * DINPROJ + DINNER + c;
        if (l >= 3) acc += w0 * base[-(size_t)3 * DINPROJ];
        if (l >= 2) acc += w1 * base[-(size_t)2 * DINPROJ];
        if (l >= 1) acc += w2 * base[-(size_t)1 * DINPROJ];
        acc += w3 * base[0];
        acc = acc / (1.f + expf(-acc));
        if (c < DINNER)            xs[(size_t)bl * DINNER + c] = acc;
        else if (c < DINNER + 64)  Bout[(size_t)bl * 64 + (c - DINNER)] = acc;
        else                       Cout[(size_t)bl * 64 + (c - DINNER - 64)] = acc;
    } else {
        int h = c - CONVDIM;
        float x = zx[(size_t)bl * DINPROJ + (DINPROJ - NHM) + h] + dtb[h];
        float sp = (x > 20.f) ? x : log1pf(expf(x));
        float A  = -expf(Alog[h]);
        dt[bl * NHM + h] = sp;
        dA[bl * NHM + h] = expf(sp * A);
    }
}

// ---------------- selective scan: 2 blocks per (b,h) (p-halves), T=32 ----------------
__global__ void __launch_bounds__(512, 1)
scan_kernel(const float* __restrict__ xs, const float* __restrict__ Bm,
            const float* __restrict__ Cm, const float* __restrict__ dt,
            const float* __restrict__ dA, const float* __restrict__ Dp,
            float* __restrict__ y)
{
    const int T = 32;
    int blk = blockIdx.x;          // 0..191
    int ph  = blk & 1;             // p half
    int bh  = blk >> 1;
    int b = bh / NHM, h = bh % NHM;
    int tid = threadIdx.x;
    int pl = tid >> 4;             // 0..31 local p row
    int nc = tid & 15;             // 0..15
    int n0 = nc * 4;
    __shared__ float sB[T][64], sC[T][64], sX[T][32], sDt[T], sDa[T];
    float s[4] = {0.f, 0.f, 0.f, 0.f};
    float Dh = Dp[h];
    size_t base = (size_t)b * LSEQ;
    const int xoff = h * 64 + ph * 32;

    for (int l0 = 0; l0 < LSEQ; l0 += T) {
        __syncthreads();
        for (int idx = tid; idx < T * 64; idx += 512) {
            int t = idx >> 6, j = idx & 63;
            size_t r = base + l0 + t;
            sB[t][j] = Bm[r * 64 + j];
            sC[t][j] = Cm[r * 64 + j];
        }
        for (int idx = tid; idx < T * 32; idx += 512) {
            int t = idx >> 5, j = idx & 31;
            sX[t][j] = xs[(base + l0 + t) * DINNER + xoff + j];
        }
        if (tid < T) {
            size_t r = base + l0 + tid;
            sDt[tid] = dt[r * NHM + h];
            sDa[tid] = dA[r * NHM + h];
        }
        __syncthreads();
#pragma unroll 4
        for (int t = 0; t < T; t++) {
            float da  = sDa[t];
            float xv  = sX[t][pl];
            float dtx = sDt[t] * xv;
            float part = 0.f;
#pragma unroll
            for (int j = 0; j < 4; j++) {
                s[j] = s[j] * da + dtx * sB[t][n0 + j];
                part += s[j] * sC[t][n0 + j];
            }
            part += __shfl_xor_sync(0xffffffffu, part, 1);
            part += __shfl_xor_sync(0xffffffffu, part, 2);
            part += __shfl_xor_sync(0xffffffffu, part, 4);
            part += __shfl_xor_sync(0xffffffffu, part, 8);
            if (nc == 0)
                y[(base + l0 + t) * DINNER + xoff + pl] = part + Dh * xv;
        }
    }
}

// ---------------- gated rmsnorm (768) -> fp16 ----------------
__global__ void rmsgate_kernel(const float* __restrict__ y, const float* __restrict__ zx,
                               const float* __restrict__ mw, __half* __restrict__ oh)
{
    int row  = blockIdx.x * 8 + (threadIdx.x >> 5);
    int lane = threadIdx.x & 31;
    if (row >= BLTOT) return;
    const float* yr = y  + (size_t)row * DINNER;
    const float* zr = zx + (size_t)row * DINPROJ;
    float g[24];
    float ss = 0.f;
#pragma unroll
    for (int i = 0; i < 6; i++) {
        int c = i * 128 + lane * 4;
        float4 yv = *(const float4*)(yr + c);
        float4 zv = *(const float4*)(zr + c);
        float z0 = zv.x / (1.f + expf(-zv.x));
        float z1 = zv.y / (1.f + expf(-zv.y));
        float z2 = zv.z / (1.f + expf(-zv.z));
        float z3 = zv.w / (1.f + expf(-zv.w));
        g[i*4+0] = yv.x * z0; g[i*4+1] = yv.y * z1;
        g[i*4+2] = yv.z * z2; g[i*4+3] = yv.w * z3;
        ss += g[i*4+0]*g[i*4+0] + g[i*4+1]*g[i*4+1] + g[i*4+2]*g[i*4+2] + g[i*4+3]*g[i*4+3];
    }
#pragma unroll
    for (int o = 16; o; o >>= 1) ss += __shfl_xor_sync(0xffffffffu, ss, o);
    float rstd = rsqrtf(ss * (1.f / DINNER) + 1e-5f);
#pragma unroll
    for (int i = 0; i < 6; i++) {
        int c = i * 128 + lane * 4;
        float4 wv = *(const float4*)(mw + c);
        size_t o0 = (size_t)row * DINNER + c;
        oh[o0+0] = __float2half_rn(g[i*4+0]*rstd*wv.x);
        oh[o0+1] = __float2half_rn(g[i*4+1]*rstd*wv.y);
        oh[o0+2] = __float2half_rn(g[i*4+2]*rstd*wv.z);
        oh[o0+3] = __float2half_rn(g[i*4+3]*rstd*wv.w);
    }
}

// ---------------- attention gate (warp per row, 12 heads, fp16 xn) ----------------
__global__ void gate_kernel(const __half* __restrict__ xn, const float* __restrict__ gw,
                            const float* __restrict__ gb, float* __restrict__ out)
{
    int row  = blockIdx.x * 8 + (threadIdx.x >> 5);
    int lane = threadIdx.x & 31;
    if (row >= BLTOT) return;
    const __half* xr = xn + (size_t)row * CDIM;
    float acc[12];
#pragma unroll
    for (int h = 0; h < 12; h++) acc[h] = 0.f;
    for (int c = lane; c < CDIM; c += 32) {
        float xv = __half2float(xr[c]);
        const float* g = gw + c * 12;
#pragma unroll
        for (int h = 0; h < 12; h++) acc[h] += xv * g[h];
    }
#pragma unroll
    for (int h = 0; h < 12; h++)
#pragma unroll
        for (int o = 16; o; o >>= 1) acc[h] += __shfl_xor_sync(0xffffffffu, acc[h], o);
    if (lane == 0) {
#pragma unroll
        for (int h = 0; h < 12; h++) {
            float a = acc[h] + gb[h];
            out[(size_t)row * NHA + h] = 1.f / (1.f + expf(-a));
        }
    }
}

// ---------------- window attention (fp16 qkv) -> gated fp16 output ----------------
__global__ void __launch_bounds__(64)
attn_kernel(const __half* __restrict__ qkv, const float* __restrict__ gate,
            __half* __restrict__ oh)
{
    int wid = blockIdx.x;
    int h   = blockIdx.y;
    int b   = wid >> 6;
    int rem = wid & 63;
    int wh  = rem >> 3;
    int ww  = rem & 7;
    __shared__ float q[49][33], k[49][33], v[49][33];
    int tid = threadIdx.x;
    for (int idx = tid; idx < 49 * 32; idx += 64) {
        int i = idx >> 5, d = idx & 31;
        int r = i / 7, c = i % 7;
        int l = (wh * 7 + r) * WW + ww * 7 + c;
        size_t rowoff = ((size_t)b * LSEQ + l) * 1152 + h * 32 + d;
        q[i][d] = __half2float(qkv[rowoff]) * 0.17677669529663687f;
        k[i][d] = __half2float(qkv[rowoff + 384]);
        v[i][d] = __half2float(qkv[rowoff + 768]);
    }
    __syncthreads();
    if (tid < 49) {
        int i = tid;
        int r = i / 7, c = i % 7;
        int l = (wh * 7 + r) * WW + ww * 7 + c;
        float sc[49];
        float mx = -1e30f;
        for (int j = 0; j < 49; j++) {
            float a = 0.f;
#pragma unroll
            for (int d = 0; d < 32; d++) a += q[i][d] * k[j][d];
            sc[j] = a;
            mx = fmaxf(mx, a);
        }
        float sum = 0.f;
        for (int j = 0; j < 49; j++) { sc[j] = expf(sc[j] - mx); sum += sc[j]; }
        float ga = gate[((size_t)b * LSEQ + l) * NHA + h];
        float inv = ga / sum;
        size_t o0 = ((size_t)b * LSEQ + l) * CDIM + h * 32;
#pragma unroll
        for (int d = 0; d < 32; d++) {
            float o = 0.f;
            for (int j = 0; j < 49; j++) o += sc[j] * v[j][d];
            oh[o0 + d] = __float2half_rn(o * inv);
        }
    }
}

// ---------------- launch ----------------
static void* devptr(const void* sym) {
    void* p = nullptr;
    cudaGetSymbolAddress(&p, sym);
    return p;
}

extern "C" void kernel_launch(void* const* d_in, const int* in_sizes, int n_in,
                              void* d_out, int out_size)
{
    const float* x       = (const float*)d_in[0];
    const float* norm1_w = (const float*)d_in[1];
    const float* norm1_b = (const float*)d_in[2];
    const float* W_in    = (const float*)d_in[3];
    const float* conv_w  = (const float*)d_in[4];
    const float* conv_b  = (const float*)d_in[5];
    const float* dt_bias = (const float*)d_in[6];
    const float* A_log   = (const float*)d_in[7];
    const float* Dp      = (const float*)d_in[8];
    const float* mnorm_w = (const float*)d_in[9];
    const float* W_out   = (const float*)d_in[10];
    const float* qkv_w   = (const float*)d_in[11];
    const float* qkv_b   = (const float*)d_in[12];
    const float* gate_w  = (const float*)d_in[13];
    const float* gate_b  = (const float*)d_in[14];
    const float* proj_w  = (const float*)d_in[15];
    const float* proj_b  = (const float*)d_in[16];
    const float* fusion_w= (const float*)d_in[17];
    const float* fusion_b= (const float*)d_in[18];
    const float* norm2_w = (const float*)d_in[19];
    const float* norm2_b = (const float*)d_in[20];
    const float* fc1_w   = (const float*)d_in[21];
    const float* fc1_b   = (const float*)d_in[22];
    const float* fc2_w   = (const float*)d_in[23];
    const float* fc2_b   = (const float*)d_in[24];
    float* out = (float*)d_out;

    cudaFuncSetAttribute(mma_gemm, cudaFuncAttributeMaxDynamicSharedMemorySize, GEMM_SMEM);

    float* p_zx  = (float*)devptr(g_zx);
    float* p_xs  = (float*)devptr(g_xs);
    float* p_Bm  = (float*)devptr(g_Bm);
    float* p_Cm  = (float*)devptr(g_Cm);
    float* p_dt  = (float*)devptr(g_dt);
    float* p_dA  = (float*)devptr(g_dA);
    float* p_y   = (float*)devptr(g_y);
    float* p_gt  = (float*)devptr(g_gate);
    float* p_x2  = (float*)devptr(g_x2);

    __half* xn_h  = (__half*)devptr(b_xn);
    __half* gh    = (__half*)devptr(b_g);
    __half* ag_h  = (__half*)devptr(b_ag);
    __half* cat_h = (__half*)devptr(b_cat);
    __half* h1_h  = (__half*)devptr(b_h1);
    __half* xn2_h = (__half*)devptr(b_xn2);
    __half* qkv_h = (__half*)devptr(b_qkv);

    __half* pw_in  = (__half*)devptr(w_in);
    __half* pw_qkv = (__half*)devptr(w_qkv);
    __half* pw_out = (__half*)devptr(w_out);
    __half* pw_prj = (__half*)devptr(w_prj);
    __half* pw_fus = (__half*)devptr(w_fus);
    __half* pw_fc1 = (__half*)devptr(w_fc1);
    __half* pw_fc2 = (__half*)devptr(w_fc2);

    // weight transpose + fp16
    {
        auto wc = [](const float* W, __half* o, int K, int N) {
            long tot = (long)K * N;
            wconv_kernel<<<(unsigned)((tot + 255) / 256), 256>>>(W, o, K, N);
        };
        wc(W_in,     pw_in,  CDIM,   DINPROJ);
        wc(qkv_w,    pw_qkv, CDIM,   1152);
        wc(W_out,    pw_out, DINNER, CDIM);
        wc(proj_w,   pw_prj, CDIM,   CDIM);
        wc(fusion_w, pw_fus, DINNER, CDIM);
        wc(fc1_w,    pw_fc1, CDIM,   1536);
        wc(fc2_w,    pw_fc2, 1536,   CDIM);
    }

    // 1) norm1 -> fp16
    ln_kernel<<<BLTOT / 8, 256>>>(x, norm1_w, norm1_b, xn_h);

    // 2) in_proj -> zx (fp32)
    mma_gemm<<<dim3(14, MTILES), 256, GEMM_SMEM>>>(xn_h, pw_in,
        nullptr, nullptr, p_zx, nullptr, 0, BLTOT, DINPROJ, CDIM, 0);

    // 3) fused conv + dt
    {
        long tot = (long)BLTOT * FCOLS;
        convdt_kernel<<<(unsigned)((tot + 255) / 256), 256>>>(p_zx, conv_w, conv_b,
            dt_bias, A_log, p_xs, p_Bm, p_Cm, p_dt, p_dA);
    }

    // 4) scan (2 blocks per (b,h))
    scan_kernel<<<NB * NHM * 2, 512>>>(p_xs, p_Bm, p_Cm, p_dt, p_dA, Dp, p_y);

    // 5) gated rmsnorm -> g fp16
    rmsgate_kernel<<<BLTOT / 8, 256>>>(p_y, p_zx, mnorm_w, gh);

    // 6) out_proj -> cat[:, 0:384]
    mma_gemm<<<dim3(3, MTILES), 256, GEMM_SMEM>>>(gh, pw_out,
        nullptr, nullptr, nullptr, cat_h, DINNER, BLTOT, CDIM, DINNER, 0);

    // 7) qkv -> fp16 (bias fused)
    mma_gemm<<<dim3(9, MTILES), 256, GEMM_SMEM>>>(xn_h, pw_qkv,
        qkv_b, nullptr, nullptr, qkv_h, 1152, BLTOT, 1152, CDIM, 0);

    // 8) gate + window attention -> attng fp16
    gate_kernel<<<BLTOT / 8, 256>>>(xn_h, gate_w, gate_b, p_gt);
    attn_kernel<<<dim3(NWIN, NHA), 64>>>(qkv_h, p_gt, ag_h);

    // 9) attn proj -> cat[:, 384:768]
    mma_gemm<<<dim3(3, MTILES), 256, GEMM_SMEM>>>(ag_h, pw_prj,
        proj_b, nullptr, nullptr, cat_h + CDIM, DINNER, BLTOT, CDIM, CDIM, 0);

    // 10) fusion: x2 = x + cat @ fusion_w + fusion_b  (K=768)
    mma_gemm<<<dim3(3, MTILES), 256, GEMM_SMEM>>>(cat_h, pw_fus,
        fusion_b, x, p_x2, nullptr, 0, BLTOT, CDIM, DINNER, 0);

    // 11) norm2 -> xn2 fp16
    ln_kernel<<<BLTOT / 8, 256>>>(p_x2, norm2_w, norm2_b, xn2_h);

    // 12) MLP
    mma_gemm<<<dim3(12, MTILES), 256, GEMM_SMEM>>>(xn2_h, pw_fc1,
        fc1_b, nullptr, nullptr, h1_h, 1536, BLTOT, 1536, CDIM, 1);
    mma_gemm<<<dim3(3, MTILES), 256, GEMM_SMEM>>>(h1_h, pw_fc2,
        fc2_b, p_x2, out, nullptr, 0, BLTOT, CDIM, 1536, 0);
}

// round 8
// speedup vs baseline: 1.0649x; 1.0649x over previous
#include <cuda_runtime.h>
#include <cuda_fp16.h>
#include <math.h>
#include <stdint.h>

// ---------------- problem constants ----------------
#define NB      8
#define HH      56
#define WW      56
#define LSEQ    3136
#define BLTOT   25088
#define CDIM    384
#define DINNER  768
#define DSTATE  64
#define NHM     12
#define DINPROJ 1676
#define CONVDIM 896
#define NHA     12
#define NWIN    512
#define MTILES  196   // BLTOT/128

// ---------------- fp32 scratch ----------------
__device__ float g_zx   [(size_t)BLTOT * DINPROJ];
__device__ float g_xs   [(size_t)BLTOT * DINNER];
__device__ float g_Bm   [(size_t)BLTOT * DSTATE];
__device__ float g_Cm   [(size_t)BLTOT * DSTATE];
__device__ float g_dt   [(size_t)BLTOT * NHM];
__device__ float g_dA   [(size_t)BLTOT * NHM];
__device__ float g_y    [(size_t)BLTOT * DINNER];
__device__ float g_gate [(size_t)BLTOT * NHA];
__device__ float g_x2   [(size_t)BLTOT * CDIM];

// ---------------- fp16 activation scratch ----------------
__device__ __half b_xn  [(size_t)BLTOT * CDIM];
__device__ __half b_g   [(size_t)BLTOT * DINNER];
__device__ __half b_ag  [(size_t)BLTOT * CDIM];
__device__ __half b_cat [(size_t)BLTOT * DINNER];   // [mamba | attn]
__device__ __half b_h1  [(size_t)BLTOT * 1536];
__device__ __half b_xn2 [(size_t)BLTOT * CDIM];
__device__ __half b_qkv [(size_t)BLTOT * 1152];

// ---------------- fp16 transposed weights [N][K] ----------------
__device__ __half w_in  [(size_t)DINPROJ * CDIM];
__device__ __half w_qkv [(size_t)1152 * CDIM];
__device__ __half w_out [(size_t)CDIM * DINNER];
__device__ __half w_prj [(size_t)CDIM * CDIM];
__device__ __half w_fus [(size_t)CDIM * DINNER];
__device__ __half w_fc1 [(size_t)1536 * CDIM];
__device__ __half w_fc2 [(size_t)CDIM * 1536];

__device__ __forceinline__ uint32_t smem_u32(const void* p) {
    uint32_t a;
    asm("{ .reg .u64 t; cvta.to.shared.u64 t, %1; cvt.u32.u64 %0, t; }" : "=r"(a) : "l"(p));
    return a;
}

// ================= mma.sync fp16 GEMM (round-6 winner, unchanged) =================
#define BKG   64
#define ASTR  72            // BK + 8 pad (fp16); 144B row stride
#define MATSZ (128 * ASTR)  // 9216 elems
#define STAGESZ (2 * MATSZ) // A, B
#define GEMM_SMEM (2 * STAGESZ * 2)  // 73728 bytes

__device__ __forceinline__ void ldsm4(uint32_t& r0, uint32_t& r1, uint32_t& r2, uint32_t& r3, uint32_t a) {
    asm volatile("ldmatrix.sync.aligned.m8n8.x4.shared.b16 {%0,%1,%2,%3}, [%4];"
                 : "=r"(r0), "=r"(r1), "=r"(r2), "=r"(r3) : "r"(a));
}
__device__ __forceinline__ void mma16816(float* c, const uint32_t* a, const uint32_t* b) {
    asm volatile("mma.sync.aligned.m16n8k16.row.col.f32.f16.f16.f32 "
                 "{%0,%1,%2,%3}, {%4,%5,%6,%7}, {%8,%9}, {%0,%1,%2,%3};"
                 : "+f"(c[0]), "+f"(c[1]), "+f"(c[2]), "+f"(c[3])
                 : "r"(a[0]), "r"(a[1]), "r"(a[2]), "r"(a[3]), "r"(b[0]), "r"(b[1]));
}
__device__ __forceinline__ void cpasync16(uint32_t dst, const void* src, uint32_t sz) {
    asm volatile("cp.async.cg.shared.global [%0], [%1], 16, %2;"
                 :: "r"(dst), "l"(src), "r"(sz) : "memory");
}

__global__ void __launch_bounds__(256, 2)
mma_gemm(const __half* __restrict__ Aw, const __half* __restrict__ Bw,
         const float* __restrict__ bias, const float* __restrict__ res,
         float* __restrict__ Cf, __half* __restrict__ Chalf,
         int ldh, int M, int N, int K, int act)
{
    extern __shared__ __align__(16) __half smem[];
    const int tid = threadIdx.x;
    const int wid = tid >> 5, lane = tid & 31;
    const int warp_m = wid & 1, warp_n = wid >> 1;
    const int m0 = blockIdx.y * 128, n0 = blockIdx.x * 128;

    const int lrow = tid >> 1, lseg = tid & 1;
    const bool bvalid = (n0 + lrow) < N;
    const uint32_t sbase = smem_u32(smem);

    float acc[4][4][4];
#pragma unroll
    for (int i = 0; i < 4; i++)
#pragma unroll
        for (int j = 0; j < 4; j++)
#pragma unroll
            for (int e = 0; e < 4; e++) acc[i][j][e] = 0.f;

    const int nch = K / BKG;

    auto load_stage = [&](int ch, int st) {
        const int k0 = ch * BKG;
        uint32_t so = (uint32_t)(st * STAGESZ + lrow * ASTR + lseg * 32) * 2;
        const __half* ga = Aw + (size_t)(m0 + lrow) * K + k0 + lseg * 32;
        const __half* gb = Bw + (size_t)(n0 + lrow) * K + k0 + lseg * 32;
        uint32_t bs = bvalid ? 16u : 0u;
#pragma unroll
        for (int u = 0; u < 4; u++) {
            cpasync16(sbase + so + u * 16,             ga + u * 8, 16u);
            cpasync16(sbase + so + MATSZ * 2 + u * 16, gb + u * 8, bs);
        }
    };

    load_stage(0, 0);
    asm volatile("cp.async.commit_group;" ::: "memory");

    for (int ch = 0; ch < nch; ch++) {
        const int st = ch & 1;
        if (ch + 1 < nch) load_stage(ch + 1, st ^ 1);
        asm volatile("cp.async.commit_group;" ::: "memory");
        asm volatile("cp.async.wait_group 1;" ::: "memory");
        __syncthreads();

        const uint32_t sA = sbase + (uint32_t)(st * STAGESZ) * 2;
        const uint32_t sB = sA + MATSZ * 2;
        const int lr = lane & 15;
        const int lk = (lane >> 4) << 3;

#pragma unroll
        for (int ks = 0; ks < BKG; ks += 16) {
            uint32_t bh[4][2];
#pragma unroll
            for (int np = 0; np < 2; np++) {
                uint32_t off = (uint32_t)((warp_n * 32 + np * 16 + lr) * ASTR + ks + lk) * 2;
                uint32_t r0, r1, r2, r3;
                ldsm4(r0, r1, r2, r3, sB + off);
                bh[np*2+0][0] = r0; bh[np*2+0][1] = r2;
                bh[np*2+1][0] = r1; bh[np*2+1][1] = r3;
            }
#pragma unroll
            for (int mt = 0; mt < 4; mt++) {
                uint32_t off = (uint32_t)((warp_m * 64 + mt * 16 + lr) * ASTR + ks + lk) * 2;
                uint32_t a[4];
                ldsm4(a[0], a[1], a[2], a[3], sA + off);
#pragma unroll
                for (int nt = 0; nt < 4; nt++) mma16816(acc[mt][nt], a, bh[nt]);
            }
        }
        __syncthreads();
    }

    // epilogue
    const int mrow = m0 + warp_m * 64 + (lane >> 2);
    const int ncol = n0 + warp_n * 32 + (lane & 3) * 2;
#pragma unroll
    for (int mt = 0; mt < 4; mt++) {
#pragma unroll
        for (int nt = 0; nt < 4; nt++) {
#pragma unroll
            for (int e = 0; e < 4; e++) {
                int r = mrow + mt * 16 + ((e >> 1) ? 8 : 0);
                int c = ncol + nt * 8 + (e & 1);
                if (c < N) {
                    float v = acc[mt][nt][e];
                    if (bias) v += bias[c];
                    if (act)  v = 0.5f * v * (1.f + erff(v * 0.70710678118654752f));
                    if (res)  v += res[(size_t)r * N + c];
                    if (Cf)    Cf[(size_t)r * N + c] = v;
                    if (Chalf) Chalf[(size_t)r * ldh + c] = __float2half_rn(v);
                }
            }
        }
    }
}

// ---------------- weight transpose + fp16: W[K][N] -> out[N][K] ----------------
__global__ void wconv_kernel(const float* __restrict__ W, __half* __restrict__ o, int K, int N)
{
    long idx = (long)blockIdx.x * blockDim.x + threadIdx.x;
    if (idx >= (long)K * N) return;
    int k = (int)(idx % K);
    long n = idx / K;
    o[idx] = __float2half_rn(W[(size_t)k * N + n]);
}

// ---------------- LayerNorm (384) -> fp16, warp per row ----------------
__global__ void ln_kernel(const float* __restrict__ x, const float* __restrict__ w,
                          const float* __restrict__ b, __half* __restrict__ oh)
{
    int row  = blockIdx.x * 8 + (threadIdx.x >> 5);
    int lane = threadIdx.x & 31;
    if (row >= BLTOT) return;
    const float* xr = x + (size_t)row * CDIM;
    float v[12];
    float s = 0.f;
#pragma unroll
    for (int i = 0; i < 3; i++) {
        float4 t = *(const float4*)(xr + i * 128 + lane * 4);
        v[i*4+0]=t.x; v[i*4+1]=t.y; v[i*4+2]=t.z; v[i*4+3]=t.w;
        s += t.x + t.y + t.z + t.w;
    }
#pragma unroll
    for (int o = 16; o; o >>= 1) s += __shfl_xor_sync(0xffffffffu, s, o);
    float mu = s * (1.f / CDIM);
    float ss = 0.f;
#pragma unroll
    for (int i = 0; i < 12; i++) { float d = v[i] - mu; ss += d * d; }
#pragma unroll
    for (int o = 16; o; o >>= 1) ss += __shfl_xor_sync(0xffffffffu, ss, o);
    float rstd = rsqrtf(ss * (1.f / CDIM) + 1e-5f);
#pragma unroll
    for (int i = 0; i < 3; i++) {
        int c = i * 128 + lane * 4;
        float4 wv = *(const float4*)(w + c);
        float4 bv = *(const float4*)(b + c);
        size_t o0 = (size_t)row * CDIM + c;
        oh[o0+0] = __float2half_rn((v[i*4+0]-mu)*rstd*wv.x + bv.x);
        oh[o0+1] = __float2half_rn((v[i*4+1]-mu)*rstd*wv.y + bv.y);
        oh[o0+2] = __float2half_rn((v[i*4+2]-mu)*rstd*wv.z + bv.z);
        oh[o0+3] = __float2half_rn((v[i*4+3]-mu)*rstd*wv.w + bv.w);
    }
}

// ---------------- depthwise causal conv(k=4) + SiLU, split ----------------
__global__ void conv_kernel(const float* __restrict__ zx, const float* __restrict__ cw,
                            const float* __restrict__ cb,
                            float* __restrict__ xs, float* __restrict__ Bout,
                            float* __restrict__ Cout)
{
    long idx = (long)blockIdx.x * blockDim.x + threadIdx.x;
    if (idx >= (long)BLTOT * CONVDIM) return;
    int c  = (int)(idx % CONVDIM);
    long bl = idx / CONVDIM;
    int l  = (int)(bl % LSEQ);
    float acc = cb[c];
    const float w0 = cw[c*4+0], w1 = cw[c*4+1], w2 = cw[c*4+2], w3 = cw[c*4+3];
    const float* base = zx + (size_t)bl * DINPROJ + DINNER + c;
    if (l >= 3) acc += w0 * base[-(size_t)3 * DINPROJ];
    if (l >= 2) acc += w1 * base[-(size_t)2 * DINPROJ];
    if (l >= 1) acc += w2 * base[-(size_t)1 * DINPROJ];
    acc += w3 * base[0];
    acc = acc / (1.f + expf(-acc));
    if (c < DINNER)            xs[(size_t)bl * DINNER + c] = acc;
    else if (c < DINNER + 64)  Bout[(size_t)bl * 64 + (c - DINNER)] = acc;
    else                       Cout[(size_t)bl * 64 + (c - DINNER - 64)] = acc;
}

// ---------------- dt / dA ----------------
__global__ void dt_kernel(const float* __restrict__ zx, const float* __restrict__ dtb,
                          const float* __restrict__ Alog,
                          float* __restrict__ dt, float* __restrict__ dA)
{
    long idx = (long)blockIdx.x * blockDim.x + threadIdx.x;
    if (idx >= (long)BLTOT * NHM) return;
    int h = (int)(idx % NHM);
    long bl = idx / NHM;
    float x = zx[(size_t)bl * DINPROJ + (DINPROJ - NHM) + h] + dtb[h];
    float sp = (x > 20.f) ? x : log1pf(expf(x));
    float A  = -expf(Alog[h]);
    dt[idx] = sp;
    dA[idx] = expf(sp * A);
}

// ---------------- selective scan (round-6 winner) ----------------
__global__ void __launch_bounds__(512, 1)
scan_kernel(const float* __restrict__ xs, const float* __restrict__ Bm,
            const float* __restrict__ Cm, const float* __restrict__ dt,
            const float* __restrict__ dA, const float* __restrict__ Dp,
            float* __restrict__ y)
{
    const int T = 16;
    int b = blockIdx.x / NHM;
    int h = blockIdx.x % NHM;
    int tid = threadIdx.x;
    int p  = tid >> 3;
    int nc = tid & 7;
    int n0 = nc * 8;
    __shared__ float sB[T][64], sC[T][64], sX[T][64], sDt[T], sDa[T];
    float s[8];
#pragma unroll
    for (int j = 0; j < 8; j++) s[j] = 0.f;
    float Dh = Dp[h];
    size_t base = (size_t)b * LSEQ;

    for (int l0 = 0; l0 < LSEQ; l0 += T) {
        __syncthreads();
        for (int idx = tid; idx < T * 64; idx += 512) {
            int t = idx >> 6, j = idx & 63;
            size_t r = base + l0 + t;
            sB[t][j] = Bm[r * 64 + j];
            sC[t][j] = Cm[r * 64 + j];
            sX[t][j] = xs[r * DINNER + h * 64 + j];
        }
        if (tid < T) {
            size_t r = base + l0 + tid;
            sDt[tid] = dt[r * NHM + h];
            sDa[tid] = dA[r * NHM + h];
        }
        __syncthreads();
#pragma unroll 4
        for (int t = 0; t < T; t++) {
            float da  = sDa[t];
            float dtx = sDt[t] * sX[t][p];
            float part = 0.f;
#pragma unroll
            for (int j = 0; j < 8; j++) {
                s[j] = s[j] * da + dtx * sB[t][n0 + j];
                part += s[j] * sC[t][n0 + j];
            }
            part += __shfl_xor_sync(0xffffffffu, part, 1);
            part += __shfl_xor_sync(0xffffffffu, part, 2);
            part += __shfl_xor_sync(0xffffffffu, part, 4);
            if (nc == 0)
                y[(base + l0 + t) * DINNER + h * 64 + p] = part + Dh * sX[t][p];
        }
    }
}

// ---------------- gated rmsnorm (768) -> fp16 ----------------
__global__ void rmsgate_kernel(const float* __restrict__ y, const float* __restrict__ zx,
                               const float* __restrict__ mw, __half* __restrict__ oh)
{
    int row  = blockIdx.x * 8 + (threadIdx.x >> 5);
    int lane = threadIdx.x & 31;
    if (row >= BLTOT) return;
    const float* yr = y  + (size_t)row * DINNER;
    const float* zr = zx + (size_t)row * DINPROJ;
    float g[24];
    float ss = 0.f;
#pragma unroll
    for (int i = 0; i < 6; i++) {
        int c = i * 128 + lane * 4;
        float4 yv = *(const float4*)(yr + c);
        float4 zv = *(const float4*)(zr + c);
        float z0 = zv.x / (1.f + expf(-zv.x));
        float z1 = zv.y / (1.f + expf(-zv.y));
        float z2 = zv.z / (1.f + expf(-zv.z));
        float z3 = zv.w / (1.f + expf(-zv.w));
        g[i*4+0] = yv.x * z0; g[i*4+1] = yv.y * z1;
        g[i*4+2] = yv.z * z2; g[i*4+3] = yv.w * z3;
        ss += g[i*4+0]*g[i*4+0] + g[i*4+1]*g[i*4+1] + g[i*4+2]*g[i*4+2] + g[i*4+3]*g[i*4+3];
    }
#pragma unroll
    for (int o = 16; o; o >>= 1) ss += __shfl_xor_sync(0xffffffffu, ss, o);
    float rstd = rsqrtf(ss * (1.f / DINNER) + 1e-5f);
#pragma unroll
    for (int i = 0; i < 6; i++) {
        int c = i * 128 + lane * 4;
        float4 wv = *(const float4*)(mw + c);
        size_t o0 = (size_t)row * DINNER + c;
        oh[o0+0] = __float2half_rn(g[i*4+0]*rstd*wv.x);
        oh[o0+1] = __float2half_rn(g[i*4+1]*rstd*wv.y);
        oh[o0+2] = __float2half_rn(g[i*4+2]*rstd*wv.z);
        oh[o0+3] = __float2half_rn(g[i*4+3]*rstd*wv.w);
    }
}

// ---------------- attention gate (warp per row, 12 heads, fp16 xn) ----------------
__global__ void gate_kernel(const __half* __restrict__ xn, const float* __restrict__ gw,
                            const float* __restrict__ gb, float* __restrict__ out)
{
    int row  = blockIdx.x * 8 + (threadIdx.x >> 5);
    int lane = threadIdx.x & 31;
    if (row >= BLTOT) return;
    const __half* xr = xn + (size_t)row * CDIM;
    float acc[12];
#pragma unroll
    for (int h = 0; h < 12; h++) acc[h] = 0.f;
    for (int c = lane; c < CDIM; c += 32) {
        float xv = __half2float(xr[c]);
        const float* g = gw + c * 12;
#pragma unroll
        for (int h = 0; h < 12; h++) acc[h] += xv * g[h];
    }
#pragma unroll
    for (int h = 0; h < 12; h++)
#pragma unroll
        for (int o = 16; o; o >>= 1) acc[h] += __shfl_xor_sync(0xffffffffu, acc[h], o);
    if (lane == 0) {
#pragma unroll
        for (int h = 0; h < 12; h++) {
            float a = acc[h] + gb[h];
            out[(size_t)row * NHA + h] = 1.f / (1.f + expf(-a));
        }
    }
}

// ---------------- window attention (fp16 qkv) -> gated fp16 output ----------------
__global__ void __launch_bounds__(64)
attn_kernel(const __half* __restrict__ qkv, const float* __restrict__ gate,
            __half* __restrict__ oh)
{
    int wid = blockIdx.x;
    int h   = blockIdx.y;
    int b   = wid >> 6;
    int rem = wid & 63;
    int wh  = rem >> 3;
    int ww  = rem & 7;
    __shared__ float q[49][33], k[49][33], v[49][33];
    int tid = threadIdx.x;
    for (int idx = tid; idx < 49 * 32; idx += 64) {
        int i = idx >> 5, d = idx & 31;
        int r = i / 7, c = i % 7;
        int l = (wh * 7 + r) * WW + ww * 7 + c;
        size_t rowoff = ((size_t)b * LSEQ + l) * 1152 + h * 32 + d;
        q[i][d] = __half2float(qkv[rowoff]) * 0.17677669529663687f;
        k[i][d] = __half2float(qkv[rowoff + 384]);
        v[i][d] = __half2float(qkv[rowoff + 768]);
    }
    __syncthreads();
    if (tid < 49) {
        int i = tid;
        int r = i / 7, c = i % 7;
        int l = (wh * 7 + r) * WW + ww * 7 + c;
        float sc[49];
        float mx = -1e30f;
        for (int j = 0; j < 49; j++) {
            float a = 0.f;
#pragma unroll
            for (int d = 0; d < 32; d++) a += q[i][d] * k[j][d];
            sc[j] = a;
            mx = fmaxf(mx, a);
        }
        float sum = 0.f;
        for (int j = 0; j < 49; j++) { sc[j] = expf(sc[j] - mx); sum += sc[j]; }
        float ga = gate[((size_t)b * LSEQ + l) * NHA + h];
        float inv = ga / sum;
        size_t o0 = ((size_t)b * LSEQ + l) * CDIM + h * 32;
#pragma unroll
        for (int d = 0; d < 32; d++) {
            float o = 0.f;
            for (int j = 0; j < 49; j++) o += sc[j] * v[j][d];
            oh[o0 + d] = __float2half_rn(o * inv);
        }
    }
}

// ---------------- launch ----------------
static void* devptr(const void* sym) {
    void* p = nullptr;
    cudaGetSymbolAddress(&p, sym);
    return p;
}

extern "C" void kernel_launch(void* const* d_in, const int* in_sizes, int n_in,
                              void* d_out, int out_size)
{
    const float* x       = (const float*)d_in[0];
    const float* norm1_w = (const float*)d_in[1];
    const float* norm1_b = (const float*)d_in[2];
    const float* W_in    = (const float*)d_in[3];
    const float* conv_w  = (const float*)d_in[4];
    const float* conv_b  = (const float*)d_in[5];
    const float* dt_bias = (const float*)d_in[6];
    const float* A_log   = (const float*)d_in[7];
    const float* Dp      = (const float*)d_in[8];
    const float* mnorm_w = (const float*)d_in[9];
    const float* W_out   = (const float*)d_in[10];
    const float* qkv_w   = (const float*)d_in[11];
    const float* qkv_b   = (const float*)d_in[12];
    const float* gate_w  = (const float*)d_in[13];
    const float* gate_b  = (const float*)d_in[14];
    const float* proj_w  = (const float*)d_in[15];
    const float* proj_b  = (const float*)d_in[16];
    const float* fusion_w= (const float*)d_in[17];
    const float* fusion_b= (const float*)d_in[18];
    const float* norm2_w = (const float*)d_in[19];
    const float* norm2_b = (const float*)d_in[20];
    const float* fc1_w   = (const float*)d_in[21];
    const float* fc1_b   = (const float*)d_in[22];
    const float* fc2_w   = (const float*)d_in[23];
    const float* fc2_b   = (const float*)d_in[24];
    float* out = (float*)d_out;

    cudaFuncSetAttribute(mma_gemm, cudaFuncAttributeMaxDynamicSharedMemorySize, GEMM_SMEM);

    float* p_zx  = (float*)devptr(g_zx);
    float* p_xs  = (float*)devptr(g_xs);
    float* p_Bm  = (float*)devptr(g_Bm);
    float* p_Cm  = (float*)devptr(g_Cm);
    float* p_dt  = (float*)devptr(g_dt);
    float* p_dA  = (float*)devptr(g_dA);
    float* p_y   = (float*)devptr(g_y);
    float* p_gt  = (float*)devptr(g_gate);
    float* p_x2  = (float*)devptr(g_x2);

    __half* xn_h  = (__half*)devptr(b_xn);
    __half* gh    = (__half*)devptr(b_g);
    __half* ag_h  = (__half*)devptr(b_ag);
    __half* cat_h = (__half*)devptr(b_cat);
    __half* h1_h  = (__half*)devptr(b_h1);
    __half* xn2_h = (__half*)devptr(b_xn2);
    __half* qkv_h = (__half*)devptr(b_qkv);

    __half* pw_in  = (__half*)devptr(w_in);
    __half* pw_qkv = (__half*)devptr(w_qkv);
    __half* pw_out = (__half*)devptr(w_out);
    __half* pw_prj = (__half*)devptr(w_prj);
    __half* pw_fus = (__half*)devptr(w_fus);
    __half* pw_fc1 = (__half*)devptr(w_fc1);
    __half* pw_fc2 = (__half*)devptr(w_fc2);

    // weight transpose + fp16
    {
        auto wc = [](const float* W, __half* o, int K, int N) {
            long tot = (long)K * N;
            wconv_kernel<<<(unsigned)((tot + 255) / 256), 256>>>(W, o, K, N);
        };
        wc(W_in,     pw_in,  CDIM,   DINPROJ);
        wc(qkv_w,    pw_qkv, CDIM,   1152);
        wc(W_out,    pw_out, DINNER, CDIM);
        wc(proj_w,   pw_prj, CDIM,   CDIM);
        wc(fusion_w, pw_fus, DINNER, CDIM);
        wc(fc1_w,    pw_fc1, CDIM,   1536);
        wc(fc2_w,    pw_fc2, 1536,   CDIM);
    }

    // 1) norm1 -> fp16
    ln_kernel<<<BLTOT / 8, 256>>>(x, norm1_w, norm1_b, xn_h);

    // 2) in_proj -> zx (fp32)
    mma_gemm<<<dim3(14, MTILES), 256, GEMM_SMEM>>>(xn_h, pw_in,
        nullptr, nullptr, p_zx, nullptr, 0, BLTOT, DINPROJ, CDIM, 0);

    // 3) conv + dt
    {
        long tot = (long)BLTOT * CONVDIM;
        conv_kernel<<<(unsigned)((tot + 255) / 256), 256>>>(p_zx, conv_w, conv_b, p_xs, p_Bm, p_Cm);
        long tot2 = (long)BLTOT * NHM;
        dt_kernel<<<(unsigned)((tot2 + 255) / 256), 256>>>(p_zx, dt_bias, A_log, p_dt, p_dA);
    }

    // 4) scan
    scan_kernel<<<NB * NHM, 512>>>(p_xs, p_Bm, p_Cm, p_dt, p_dA, Dp, p_y);

    // 5) gated rmsnorm -> g fp16
    rmsgate_kernel<<<BLTOT / 8, 256>>>(p_y, p_zx, mnorm_w, gh);

    // 6) out_proj -> cat[:, 0:384]
    mma_gemm<<<dim3(3, MTILES), 256, GEMM_SMEM>>>(gh, pw_out,
        nullptr, nullptr, nullptr, cat_h, DINNER, BLTOT, CDIM, DINNER, 0);

    // 7) qkv -> fp16 (bias fused)
    mma_gemm<<<dim3(9, MTILES), 256, GEMM_SMEM>>>(xn_h, pw_qkv,
        qkv_b, nullptr, nullptr, qkv_h, 1152, BLTOT, 1152, CDIM, 0);

    // 8) gate + window attention -> attng fp16
    gate_kernel<<<BLTOT / 8, 256>>>(xn_h, gate_w, gate_b, p_gt);
    attn_kernel<<<dim3(NWIN, NHA), 64>>>(qkv_h, p_gt, ag_h);

    // 9) attn proj -> cat[:, 384:768]
    mma_gemm<<<dim3(3, MTILES), 256, GEMM_SMEM>>>(ag_h, pw_prj,
        proj_b, nullptr, nullptr, cat_h + CDIM, DINNER, BLTOT, CDIM, CDIM, 0);

    // 10) fusion: x2 = x + cat @ fusion_w + fusion_b  (K=768)
    mma_gemm<<<dim3(3, MTILES), 256, GEMM_SMEM>>>(cat_h, pw_fus,
        fusion_b, x, p_x2, nullptr, 0, BLTOT, CDIM, DINNER, 0);

    // 11) norm2 -> xn2 fp16
    ln_kernel<<<BLTOT / 8, 256>>>(p_x2, norm2_w, norm2_b, xn2_h);

    // 12) MLP
    mma_gemm<<<dim3(12, MTILES), 256, GEMM_SMEM>>>(xn2_h, pw_fc1,
        fc1_b, nullptr, nullptr, h1_h, 1536, BLTOT, 1536, CDIM, 1);
    mma_gemm<<<dim3(3, MTILES), 256, GEMM_SMEM>>>(h1_h, pw_fc2,
        fc2_b, p_x2, out, nullptr, 0, BLTOT, CDIM, 1536, 0);
}